// round 14
// baseline (speedup 1.0000x reference)
#include <cuda_runtime.h>

// Correlation cost volume, max_disp=4.
// out[b, dx*9+dy, h, w] = (1/128) * sum_c x1[b,c,h,w] * x2pad[b,c,h+dx,w+dy]
// x1,x2: [8,128,128,128] f32 ; out: [8,81,128,128] f32.
//
// R14: SMSP-balanced split. 8 consumer warps (dxi 0..7, exactly 2 per SMSP,
// 8px/thread) + 2 hybrid warps that BOTH produce (cp.async fills, 2-chunk
// lookahead cursor) AND compute dxi=8 (one row each, 4px/thread).
// FFMA2 runs at rt=3 (3 distinct even/odd operand regs), so the old 3-consumer
// SMSP was the wall (324 cyc/ch); balancing drops it to ~216+eps.

#define CC_C   128
#define CC_H   128
#define CC_W   128
#define CC_B   8
#define CC_D   4
#define CC_ND  9
#define CC_NOFF 81
#define CC_TH  2
#define CC_PX  8
#define CC_CCH 8
#define CC_NCHUNK (CC_C / CC_CCH)     // 16
#define CC_X2R (CC_TH + 2*CC_D)       // 10
#define CC_X2WP 160                   // padded row: 640 B (data floats [4,132))
#define NSTAGE 3
#define NCW    8                      // consumer warps (dxi 0..7)
#define NPT    64                     // hybrid threads (2 warps)
#define NTH    (NCW*32 + NPT)         // 320
#define NBLK   148
#define NTILES (CC_B * (CC_H / CC_TH))  // 512

#define X1B   (CC_CCH*CC_TH*CC_W*4)        // 8192 B / stage
#define X2B   (CC_CCH*CC_X2R*CC_X2WP*4)    // 51200 B / stage
#define STB   (X1B + X2B)                  // 59392 B / stage
#define DATAB 64
#define SMEM_BYTES (DATAB + NSTAGE * STB)  // 178240 B

#define N_X1F4 (X1B/16)                    // 512 -> 8 per hybrid thread
#define N_X2F4 (CC_CCH*CC_X2R*(CC_W/4))    // 2560 -> 40 per hybrid thread
#define CHUNK_SRC_BYTES (CC_CCH*CC_H*CC_W*4)

#define MB_FULL(s)  ((s) * 8)
#define MB_EMPTY(s) (32 + (s) * 8)

typedef unsigned long long u64t;

#define FMA2(acc, a, b) \
    asm("fma.rn.f32x2 %0, %1, %2, %0;" : "+l"(acc) : "l"(a), "l"(b))
#define PACK2(d, lo, hi) \
    asm("mov.b64 %0, {%1, %2};" : "=l"(d) : "f"(lo), "f"(hi))
#define UNPACK2(lo, hi, v) \
    asm("mov.b64 {%0, %1}, %2;" : "=f"(lo), "=f"(hi) : "l"(v))

__device__ __forceinline__ void cp16(unsigned dst, const void* src, int src_bytes) {
    asm volatile("cp.async.cg.shared.global [%0], [%1], 16, %2;\n"
                 :: "r"(dst), "l"(src), "r"(src_bytes));
}
__device__ __forceinline__ unsigned swz(unsigned a) { return a ^ ((a >> 3) & 0x10u); }

__device__ __forceinline__ void mbar_init(unsigned addr, unsigned cnt) {
    asm volatile("mbarrier.init.shared.b64 [%0], %1;" :: "r"(addr), "r"(cnt) : "memory");
}
__device__ __forceinline__ void mbar_arrive(unsigned addr) {
    asm volatile("mbarrier.arrive.shared.b64 _, [%0];" :: "r"(addr) : "memory");
}
__device__ __forceinline__ void cpasync_arrive_noinc(unsigned addr) {
    asm volatile("cp.async.mbarrier.arrive.noinc.shared::cta.b64 [%0];"
                 :: "r"(addr) : "memory");
}
__device__ __forceinline__ void mbar_wait_acq(unsigned addr, unsigned parity) {
    asm volatile(
        "{\n\t.reg .pred P;\n\t"
        "WL_%=:\n\t"
        "mbarrier.try_wait.parity.acquire.cta.shared::cta.b64 P, [%0], %1, 0x989680;\n\t"
        "@P bra.uni WD_%=;\n\tbra.uni WL_%=;\n\tWD_%=:\n\t}"
        :: "r"(addr), "r"(parity) : "memory");
}
__device__ __forceinline__ void mbar_wait_rlx(unsigned addr, unsigned parity) {
    asm volatile(
        "{\n\t.reg .pred P;\n\t"
        "WL_%=:\n\t"
        "mbarrier.try_wait.parity.relaxed.cta.shared::cta.b64 P, [%0], %1, 0x989680;\n\t"
        "@P bra.uni WD_%=;\n\tbra.uni WL_%=;\n\tWD_%=:\n\t}"
        :: "r"(addr), "r"(parity) : "memory");
}

// Paced per-chunk fill (R10 style: recompute indices; ALU spacing avoids
// bursting the smem write port against consumer LDS).
__device__ __forceinline__ void producer_fill(unsigned smem_u32, unsigned stoff,
                                              const char* bx1, const char* bx2,
                                              unsigned coff, int ptid, int h0)
{
#pragma unroll
    for (int k = 0; k < N_X1F4 / NPT; ++k) {
        const int i = ptid + k * NPT;
        const int c = i >> 6, rem = i & 63, hh = rem >> 5, q = rem & 31;
        const unsigned rel = (unsigned)((c * CC_TH + hh) * CC_W + 4 * q) * 4u;
        cp16(smem_u32 + stoff + swz(rel),
             bx1 + ((size_t)(c * CC_H + h0 + hh) * CC_W + 4 * q) * 4 + coff, 16);
    }
#pragma unroll
    for (int k = 0; k < N_X2F4 / NPT; ++k) {
        const int j = ptid + k * NPT;
        const int c = j / (CC_X2R * 32);
        const int rem = j - c * (CC_X2R * 32);
        const int r = rem >> 5, q = rem & 31;
        const int grow = h0 - CC_D + r;
        const int ok = (grow >= 0) && (grow < CC_H);
        const unsigned rel =
            (unsigned)(X1B + ((c * CC_X2R + r) * CC_X2WP + CC_D + 4 * q) * 4);
        cp16(smem_u32 + stoff + swz(rel),
             bx2 + ((size_t)(c * CC_H + (ok ? grow : 0)) * CC_W + 4 * q) * 4 + coff,
             ok ? 16 : 0);
    }
}

extern "C" __global__ void __launch_bounds__(NTH, 1)
corr_kernel(const float* __restrict__ x1,
            const float* __restrict__ x2,
            float* __restrict__ out)
{
    extern __shared__ char smem_c[];
    const int tid = threadIdx.x;

    unsigned smem_u32;
    asm("{ .reg .u64 t; cvta.to.shared.u64 t, %1; cvt.u32.u64 %0, t; }"
        : "=r"(smem_u32) : "l"(smem_c));

    if (tid == 0) {
#pragma unroll
        for (int s = 0; s < NSTAGE; ++s) {
            mbar_init(smem_u32 + MB_FULL(s), NPT);
            mbar_init(smem_u32 + MB_EMPTY(s), NCW + 2);   // 8 consumers + 2 hybrids
        }
    }

    // ---- zero x2 pads once per stage ----
    for (int i = tid; i < NSTAGE * CC_CCH * CC_X2R * 2; i += NTH) {
        const int s = i / (CC_CCH * CC_X2R * 2);
        const int rem = i % (CC_CCH * CC_X2R * 2);
        const int cr = rem >> 1, side = rem & 1;
        const unsigned rel =
            (unsigned)(X1B + (cr * CC_X2WP + (side ? (CC_D + CC_W) : 0)) * 4);
        *(float4*)(smem_c + DATAB + s * STB + swz(rel)) = make_float4(0.f, 0.f, 0.f, 0.f);
    }
    __syncthreads();

    const float inv = 1.0f / (float)CC_C;

    if (tid >= NCW * 32) {
        // ============ HYBRID (2 warps): fills + dxi=8 compute ============
        const int ptid = tid - NCW * 32;   // 0..63
        const int wp   = ptid >> 5;        // 0,1 : output row within tile
        const int lane = tid & 31;

        // dxi=8 compute addresses: x1 row wp, x2 padded row wp+8, 4px/thread
        const unsigned sHA  = swz((unsigned)((wp * CC_W + 4 * lane) * 4));
        const unsigned hvb  = (unsigned)(X1B + ((wp + 8) * CC_X2WP + 4 * lane) * 4);
        const unsigned sHV0 = swz(hvb), sHV1 = swz(hvb + 16u), sHV2 = swz(hvb + 32u);

        // fill cursor (2 chunks ahead)
        int s_f = 0; unsigned ph_f = 1;
        int t_f = blockIdx.x, fc_f = 0;
        const char* bx1f = (const char*)(x1 + (size_t)(t_f >> 6) * CC_C * CC_H * CC_W);
        const char* bx2f = (const char*)(x2 + (size_t)(t_f >> 6) * CC_C * CC_H * CC_W);
        int h0f = (t_f & 63) * CC_TH;

        // prologue: fill 2 chunks
#pragma unroll
        for (int k = 0; k < NSTAGE - 1; ++k) {
            mbar_wait_rlx(smem_u32 + MB_EMPTY(s_f), ph_f);
            producer_fill(smem_u32, DATAB + (unsigned)s_f * STB, bx1f, bx2f,
                          (unsigned)fc_f * CHUNK_SRC_BYTES, ptid, h0f);
            cpasync_arrive_noinc(smem_u32 + MB_FULL(s_f));
            if (++s_f == NSTAGE) { s_f = 0; ph_f ^= 1; }
            if (++fc_f == CC_NCHUNK) {
                fc_f = 0; t_f += NBLK;
                if (t_f < NTILES) {
                    bx1f = (const char*)(x1 + (size_t)(t_f >> 6) * CC_C * CC_H * CC_W);
                    bx2f = (const char*)(x2 + (size_t)(t_f >> 6) * CC_C * CC_H * CC_W);
                    h0f = (t_f & 63) * CC_TH;
                }
            }
        }

        int s_c = 0; unsigned ph_c = 0;
        for (int t = blockIdx.x; t < NTILES; t += NBLK) {
            const int b  = t >> 6;
            const int h0 = (t & 63) * CC_TH;
            u64t acc2[CC_ND][2] = {};

            for (int cc = 0; cc < CC_NCHUNK; ++cc) {
                // fill (lookahead)
                if (t_f < NTILES) {
                    mbar_wait_rlx(smem_u32 + MB_EMPTY(s_f), ph_f);
                    producer_fill(smem_u32, DATAB + (unsigned)s_f * STB, bx1f, bx2f,
                                  (unsigned)fc_f * CHUNK_SRC_BYTES, ptid, h0f);
                    cpasync_arrive_noinc(smem_u32 + MB_FULL(s_f));
                    if (++s_f == NSTAGE) { s_f = 0; ph_f ^= 1; }
                    if (++fc_f == CC_NCHUNK) {
                        fc_f = 0; t_f += NBLK;
                        if (t_f < NTILES) {
                            bx1f = (const char*)(x1 + (size_t)(t_f >> 6) * CC_C * CC_H * CC_W);
                            bx2f = (const char*)(x2 + (size_t)(t_f >> 6) * CC_C * CC_H * CC_W);
                            h0f = (t_f & 63) * CC_TH;
                        }
                    }
                }
                // consume: dxi=8, 4px
                mbar_wait_acq(smem_u32 + MB_FULL(s_c), ph_c);
                const char* stc = smem_c + DATAB + s_c * STB;
#pragma unroll
                for (int c = 0; c < CC_CCH; ++c) {
                    union { float4 f4;    float sv[4];  u64t u[2]; } A;
                    union { float4 f4[3]; float sv[12]; u64t u[6]; } V;
                    A.f4    = *(const float4*)(stc + sHA  + c * 1024);
                    V.f4[0] = *(const float4*)(stc + sHV0 + c * 6400);
                    V.f4[1] = *(const float4*)(stc + sHV1 + c * 6400);
                    V.f4[2] = *(const float4*)(stc + sHV2 + c * 6400);
                    u64t o[5];
#pragma unroll
                    for (int m = 0; m < 5; ++m)
                        PACK2(o[m], V.sv[2 * m + 1], V.sv[2 * m + 2]);
#pragma unroll
                    for (int tt = 0; tt < 5; ++tt) {       // even dy = 2tt
                        FMA2(acc2[2 * tt][0], A.u[0], V.u[tt]);
                        FMA2(acc2[2 * tt][1], A.u[1], V.u[tt + 1]);
                    }
#pragma unroll
                    for (int tt = 0; tt < 4; ++tt) {       // odd dy = 2tt+1
                        FMA2(acc2[2 * tt + 1][0], A.u[0], o[tt]);
                        FMA2(acc2[2 * tt + 1][1], A.u[1], o[tt + 1]);
                    }
                }
                if (lane == 0) mbar_arrive(smem_u32 + MB_EMPTY(s_c));
                if (++s_c == NSTAGE) { s_c = 0; ph_c ^= 1; }
            }

            // dxi=8 epilogue: row h0+wp, 4px/thread
            const int h = h0 + wp;
#pragma unroll
            for (int dy = 0; dy < CC_ND; ++dy) {
                float f0, f1, f2, f3;
                UNPACK2(f0, f1, acc2[dy][0]);
                UNPACK2(f2, f3, acc2[dy][1]);
                float4 r;
                r.x = f0 * inv; r.y = f1 * inv; r.z = f2 * inv; r.w = f3 * inv;
                *(float4*)&out[(((size_t)(b * CC_NOFF + 72 + dy) * CC_H) + h) * CC_W
                               + 4 * lane] = r;
            }
        }
        return;
    }

    // ============ CONSUMER (8 warps, warp = dxi 0..7) ============
    const int warp = tid >> 5;        // dxi 0..7
    const int lane = tid & 31;
    const int hl   = lane >> 4;       // 0..1 local row
    const int wg   = lane & 15;       // 8px group
    const int dxi  = warp;

    const unsigned x1rel0 = (unsigned)(hl * CC_W + CC_PX * wg) * 4u;
    const unsigned x2rel0 = (unsigned)(X1B + ((hl + dxi) * CC_X2WP + CC_PX * wg) * 4);
    const unsigned sA0 = swz(x1rel0),        sA1 = swz(x1rel0 + 16u);
    const unsigned sV0 = swz(x2rel0),        sV1 = swz(x2rel0 + 16u);
    const unsigned sV2 = swz(x2rel0 + 32u),  sV3 = swz(x2rel0 + 48u);

    int s = 0; unsigned ph = 0;

    for (int t = blockIdx.x; t < NTILES; t += NBLK) {
        const int b  = t >> 6;
        const int h0 = (t & 63) * CC_TH;

        u64t acc2[CC_ND][4] = {};

        for (int chunk = 0; chunk < CC_NCHUNK; ++chunk) {
            mbar_wait_acq(smem_u32 + MB_FULL(s), ph);
            const char* stc = smem_c + DATAB + s * STB;

#pragma unroll
            for (int c = 0; c < CC_CCH; ++c) {
                union { float4 f4[2]; float sv[8];  u64t u[4]; } A;
                union { float4 f4[4]; float sv[16]; u64t u[8]; } V;
                A.f4[0] = *(const float4*)(stc + sA0 + c * 1024);
                A.f4[1] = *(const float4*)(stc + sA1 + c * 1024);
                V.f4[0] = *(const float4*)(stc + sV0 + c * 6400);
                V.f4[1] = *(const float4*)(stc + sV1 + c * 6400);
                V.f4[2] = *(const float4*)(stc + sV2 + c * 6400);
                V.f4[3] = *(const float4*)(stc + sV3 + c * 6400);

                u64t o[7];
#pragma unroll
                for (int m = 0; m < 7; ++m)
                    PACK2(o[m], V.sv[2 * m + 1], V.sv[2 * m + 2]);

#pragma unroll
                for (int tt = 0; tt < 5; ++tt)       // even dy = 2tt
#pragma unroll
                    for (int j = 0; j < 4; ++j)
                        FMA2(acc2[2 * tt][j], A.u[j], V.u[tt + j]);
#pragma unroll
                for (int tt = 0; tt < 4; ++tt)       // odd dy = 2tt+1
#pragma unroll
                    for (int j = 0; j < 4; ++j)
                        FMA2(acc2[2 * tt + 1][j], A.u[j], o[tt + j]);
            }
            if (lane == 0) mbar_arrive(smem_u32 + MB_EMPTY(s));
            if (++s == NSTAGE) { s = 0; ph ^= 1; }
        }

        // ---- per-tile epilogue ----
        const int h = h0 + hl;
#pragma unroll
        for (int dy = 0; dy < CC_ND; ++dy) {
            float f[8];
#pragma unroll
            for (int j = 0; j < 4; ++j)
                UNPACK2(f[2 * j], f[2 * j + 1], acc2[dy][j]);
            float4 r0, r1;
            r0.x = f[0] * inv; r0.y = f[1] * inv; r0.z = f[2] * inv; r0.w = f[3] * inv;
            r1.x = f[4] * inv; r1.y = f[5] * inv; r1.z = f[6] * inv; r1.w = f[7] * inv;
            float* op = &out[(((size_t)(b * CC_NOFF + dxi * CC_ND + dy) * CC_H) + h) * CC_W
                             + CC_PX * wg];
            ((float4*)op)[0] = r0;
            ((float4*)op)[1] = r1;
        }
    }
}

extern "C" void kernel_launch(void* const* d_in, const int* in_sizes, int n_in,
                              void* d_out, int out_size)
{
    const float* x1 = (const float*)d_in[0];
    const float* x2 = (const float*)d_in[1];
    float* out = (float*)d_out;

    cudaFuncSetAttribute(corr_kernel,
                         cudaFuncAttributeMaxDynamicSharedMemorySize, SMEM_BYTES);
    corr_kernel<<<NBLK, NTH, SMEM_BYTES>>>(x1, x2, out);
}

// round 15
// speedup vs baseline: 1.5752x; 1.5752x over previous
#include <cuda_runtime.h>

// Correlation cost volume, max_disp=4.
// out[b, dx*9+dy, h, w] = (1/128) * sum_c x1[b,c,h,w] * x2pad[b,c,h+dx,w+dy]
// x1,x2: [8,128,128,128] f32 ; out: [8,81,128,128] f32.
//
// R15 = R10 (persistent, paced producers, simple fat-consumer core) with an
// SMSP-balanced roster: 8 fat consumers (dxi 0..7, 8px) + 2 LIGHT PURE
// consumers (dxi=8, one row each, 4px) + 2 dedicated producers = 12 warps.
// FFMA2 rt=3 makes a 3-fat-warp SMSP the wall (324 cyc/ch); this roster caps
// every SMSP at ~270.

#define CC_C   128
#define CC_H   128
#define CC_W   128
#define CC_B   8
#define CC_D   4
#define CC_ND  9
#define CC_NOFF 81
#define CC_TH  2
#define CC_PX  8
#define CC_CCH 8
#define CC_NCHUNK (CC_C / CC_CCH)     // 16
#define CC_X2R (CC_TH + 2*CC_D)       // 10
#define CC_X2WP 160                   // padded row: 640 B (data floats [4,132))
#define NSTAGE 3
#define NFAT   8                      // fat consumer warps (dxi 0..7)
#define NLITE  2                      // light consumer warps (dxi=8 rows)
#define NCONS  (NFAT + NLITE)         // 10 consumer warps
#define NPT    64                     // producer threads (2 warps)
#define NTH    (NCONS*32 + NPT)       // 384
#define NBLK   148
#define NTILES (CC_B * (CC_H / CC_TH))  // 512

#define X1B   (CC_CCH*CC_TH*CC_W*4)        // 8192 B / stage
#define X2B   (CC_CCH*CC_X2R*CC_X2WP*4)    // 51200 B / stage
#define STB   (X1B + X2B)                  // 59392 B / stage
#define DATAB 64
#define SMEM_BYTES (DATAB + NSTAGE * STB)  // 178240 B

#define N_X1F4 (X1B/16)                    // 512 -> 8 per producer thread
#define N_X2F4 (CC_CCH*CC_X2R*(CC_W/4))    // 2560 -> 40 per producer thread
#define CHUNK_SRC_BYTES (CC_CCH*CC_H*CC_W*4)

#define MB_FULL(s)  ((s) * 8)
#define MB_EMPTY(s) (32 + (s) * 8)

typedef unsigned long long u64t;

#define FMA2(acc, a, b) \
    asm("fma.rn.f32x2 %0, %1, %2, %0;" : "+l"(acc) : "l"(a), "l"(b))
#define PACK2(d, lo, hi) \
    asm("mov.b64 %0, {%1, %2};" : "=l"(d) : "f"(lo), "f"(hi))
#define UNPACK2(lo, hi, v) \
    asm("mov.b64 {%0, %1}, %2;" : "=f"(lo), "=f"(hi) : "l"(v))

__device__ __forceinline__ void cp16(unsigned dst, const void* src, int src_bytes) {
    asm volatile("cp.async.cg.shared.global [%0], [%1], 16, %2;\n"
                 :: "r"(dst), "l"(src), "r"(src_bytes));
}
__device__ __forceinline__ unsigned swz(unsigned a) { return a ^ ((a >> 3) & 0x10u); }

__device__ __forceinline__ void mbar_init(unsigned addr, unsigned cnt) {
    asm volatile("mbarrier.init.shared.b64 [%0], %1;" :: "r"(addr), "r"(cnt) : "memory");
}
__device__ __forceinline__ void mbar_arrive(unsigned addr) {
    asm volatile("mbarrier.arrive.shared.b64 _, [%0];" :: "r"(addr) : "memory");
}
__device__ __forceinline__ void cpasync_arrive_noinc(unsigned addr) {
    asm volatile("cp.async.mbarrier.arrive.noinc.shared::cta.b64 [%0];"
                 :: "r"(addr) : "memory");
}
__device__ __forceinline__ void mbar_wait_acq(unsigned addr, unsigned parity) {
    asm volatile(
        "{\n\t.reg .pred P;\n\t"
        "WL_%=:\n\t"
        "mbarrier.try_wait.parity.acquire.cta.shared::cta.b64 P, [%0], %1, 0x989680;\n\t"
        "@P bra.uni WD_%=;\n\tbra.uni WL_%=;\n\tWD_%=:\n\t}"
        :: "r"(addr), "r"(parity) : "memory");
}
__device__ __forceinline__ void mbar_wait_rlx(unsigned addr, unsigned parity) {
    asm volatile(
        "{\n\t.reg .pred P;\n\t"
        "WL_%=:\n\t"
        "mbarrier.try_wait.parity.relaxed.cta.shared::cta.b64 P, [%0], %1, 0x989680;\n\t"
        "@P bra.uni WD_%=;\n\tbra.uni WL_%=;\n\tWD_%=:\n\t}"
        :: "r"(addr), "r"(parity) : "memory");
}

// Paced per-chunk fill (R10 style: recompute indices each chunk).
__device__ __forceinline__ void producer_fill(unsigned smem_u32, unsigned stoff,
                                              const char* bx1, const char* bx2,
                                              unsigned coff, int ptid, int h0)
{
#pragma unroll
    for (int k = 0; k < N_X1F4 / NPT; ++k) {
        const int i = ptid + k * NPT;
        const int c = i >> 6, rem = i & 63, hh = rem >> 5, q = rem & 31;
        const unsigned rel = (unsigned)((c * CC_TH + hh) * CC_W + 4 * q) * 4u;
        cp16(smem_u32 + stoff + swz(rel),
             bx1 + ((size_t)(c * CC_H + h0 + hh) * CC_W + 4 * q) * 4 + coff, 16);
    }
#pragma unroll
    for (int k = 0; k < N_X2F4 / NPT; ++k) {
        const int j = ptid + k * NPT;
        const int c = j / (CC_X2R * 32);
        const int rem = j - c * (CC_X2R * 32);
        const int r = rem >> 5, q = rem & 31;
        const int grow = h0 - CC_D + r;
        const int ok = (grow >= 0) && (grow < CC_H);
        const unsigned rel =
            (unsigned)(X1B + ((c * CC_X2R + r) * CC_X2WP + CC_D + 4 * q) * 4);
        cp16(smem_u32 + stoff + swz(rel),
             bx2 + ((size_t)(c * CC_H + (ok ? grow : 0)) * CC_W + 4 * q) * 4 + coff,
             ok ? 16 : 0);
    }
}

extern "C" __global__ void __launch_bounds__(NTH, 1)
corr_kernel(const float* __restrict__ x1,
            const float* __restrict__ x2,
            float* __restrict__ out)
{
    extern __shared__ char smem_c[];
    const int tid = threadIdx.x;

    unsigned smem_u32;
    asm("{ .reg .u64 t; cvta.to.shared.u64 t, %1; cvt.u32.u64 %0, t; }"
        : "=r"(smem_u32) : "l"(smem_c));

    if (tid == 0) {
#pragma unroll
        for (int s = 0; s < NSTAGE; ++s) {
            mbar_init(smem_u32 + MB_FULL(s), NPT);
            mbar_init(smem_u32 + MB_EMPTY(s), NCONS);   // elected per-warp arrives
        }
    }

    // ---- zero x2 pads once per stage ----
    for (int i = tid; i < NSTAGE * CC_CCH * CC_X2R * 2; i += NTH) {
        const int s = i / (CC_CCH * CC_X2R * 2);
        const int rem = i % (CC_CCH * CC_X2R * 2);
        const int cr = rem >> 1, side = rem & 1;
        const unsigned rel =
            (unsigned)(X1B + (cr * CC_X2WP + (side ? (CC_D + CC_W) : 0)) * 4);
        *(float4*)(smem_c + DATAB + s * STB + swz(rel)) = make_float4(0.f, 0.f, 0.f, 0.f);
    }
    __syncthreads();

    const float inv = 1.0f / (float)CC_C;
    const int warp = tid >> 5;
    const int lane = tid & 31;

    if (warp >= NCONS) {
        // ================= PRODUCER (2 warps), persistent =================
        const int ptid = tid - NCONS * 32;
        int s = 0; unsigned ph = 1;       // flipped: first NSTAGE waits pass
        for (int t = blockIdx.x; t < NTILES; t += NBLK) {
            const int b  = t >> 6;
            const int h0 = (t & 63) * CC_TH;
            const char* bx1 = (const char*)(x1 + (size_t)b * CC_C * CC_H * CC_W);
            const char* bx2 = (const char*)(x2 + (size_t)b * CC_C * CC_H * CC_W);
            for (int fc = 0; fc < CC_NCHUNK; ++fc) {
                mbar_wait_rlx(smem_u32 + MB_EMPTY(s), ph);
                producer_fill(smem_u32, DATAB + (unsigned)s * STB, bx1, bx2,
                              (unsigned)fc * CHUNK_SRC_BYTES, ptid, h0);
                cpasync_arrive_noinc(smem_u32 + MB_FULL(s));
                if (++s == NSTAGE) { s = 0; ph ^= 1; }
            }
        }
        return;
    }

    if (warp >= NFAT) {
        // ========= LIGHT CONSUMER (2 warps): dxi=8, one row each, 4px =========
        const int wp = warp - NFAT;     // 0..1 local output row
        const unsigned sHA  = swz((unsigned)((wp * CC_W + 4 * lane) * 4));
        const unsigned hvb  = (unsigned)(X1B + ((wp + 8) * CC_X2WP + 4 * lane) * 4);
        const unsigned sHV0 = swz(hvb), sHV1 = swz(hvb + 16u), sHV2 = swz(hvb + 32u);

        int s = 0; unsigned ph = 0;
        for (int t = blockIdx.x; t < NTILES; t += NBLK) {
            const int b  = t >> 6;
            const int h0 = (t & 63) * CC_TH;
            u64t acc2[CC_ND][2] = {};

            for (int chunk = 0; chunk < CC_NCHUNK; ++chunk) {
                mbar_wait_acq(smem_u32 + MB_FULL(s), ph);
                const char* stc = smem_c + DATAB + s * STB;
#pragma unroll
                for (int c = 0; c < CC_CCH; ++c) {
                    union { float4 f4;    float sv[4];  u64t u[2]; } A;
                    union { float4 f4[3]; float sv[12]; u64t u[6]; } V;
                    A.f4    = *(const float4*)(stc + sHA  + c * 1024);
                    V.f4[0] = *(const float4*)(stc + sHV0 + c * 6400);
                    V.f4[1] = *(const float4*)(stc + sHV1 + c * 6400);
                    V.f4[2] = *(const float4*)(stc + sHV2 + c * 6400);
                    u64t o[5];
#pragma unroll
                    for (int m = 0; m < 5; ++m)
                        PACK2(o[m], V.sv[2 * m + 1], V.sv[2 * m + 2]);
#pragma unroll
                    for (int tt = 0; tt < 5; ++tt) {       // even dy = 2tt
                        FMA2(acc2[2 * tt][0], A.u[0], V.u[tt]);
                        FMA2(acc2[2 * tt][1], A.u[1], V.u[tt + 1]);
                    }
#pragma unroll
                    for (int tt = 0; tt < 4; ++tt) {       // odd dy = 2tt+1
                        FMA2(acc2[2 * tt + 1][0], A.u[0], o[tt]);
                        FMA2(acc2[2 * tt + 1][1], A.u[1], o[tt + 1]);
                    }
                }
                if (lane == 0) mbar_arrive(smem_u32 + MB_EMPTY(s));
                if (++s == NSTAGE) { s = 0; ph ^= 1; }
            }

            const int h = h0 + wp;
#pragma unroll
            for (int dy = 0; dy < CC_ND; ++dy) {
                float f0, f1, f2, f3;
                UNPACK2(f0, f1, acc2[dy][0]);
                UNPACK2(f2, f3, acc2[dy][1]);
                float4 r;
                r.x = f0 * inv; r.y = f1 * inv; r.z = f2 * inv; r.w = f3 * inv;
                *(float4*)&out[(((size_t)(b * CC_NOFF + 72 + dy) * CC_H) + h) * CC_W
                               + 4 * lane] = r;
            }
        }
        return;
    }

    // ============ FAT CONSUMER (8 warps, warp = dxi 0..7) ============
    const int hl   = lane >> 4;       // 0..1 local row
    const int wg   = lane & 15;       // 8px group
    const int dxi  = warp;

    const unsigned x1rel0 = (unsigned)(hl * CC_W + CC_PX * wg) * 4u;
    const unsigned x2rel0 = (unsigned)(X1B + ((hl + dxi) * CC_X2WP + CC_PX * wg) * 4);
    const unsigned sA0 = swz(x1rel0),        sA1 = swz(x1rel0 + 16u);
    const unsigned sV0 = swz(x2rel0),        sV1 = swz(x2rel0 + 16u);
    const unsigned sV2 = swz(x2rel0 + 32u),  sV3 = swz(x2rel0 + 48u);

    int s = 0; unsigned ph = 0;

    for (int t = blockIdx.x; t < NTILES; t += NBLK) {
        const int b  = t >> 6;
        const int h0 = (t & 63) * CC_TH;

        u64t acc2[CC_ND][4] = {};

        for (int chunk = 0; chunk < CC_NCHUNK; ++chunk) {
            mbar_wait_acq(smem_u32 + MB_FULL(s), ph);
            const char* stc = smem_c + DATAB + s * STB;

#pragma unroll
            for (int c = 0; c < CC_CCH; ++c) {
                union { float4 f4[2]; float sv[8];  u64t u[4]; } A;
                union { float4 f4[4]; float sv[16]; u64t u[8]; } V;
                A.f4[0] = *(const float4*)(stc + sA0 + c * 1024);
                A.f4[1] = *(const float4*)(stc + sA1 + c * 1024);
                V.f4[0] = *(const float4*)(stc + sV0 + c * 6400);
                V.f4[1] = *(const float4*)(stc + sV1 + c * 6400);
                V.f4[2] = *(const float4*)(stc + sV2 + c * 6400);
                V.f4[3] = *(const float4*)(stc + sV3 + c * 6400);

                u64t o[7];
#pragma unroll
                for (int m = 0; m < 7; ++m)
                    PACK2(o[m], V.sv[2 * m + 1], V.sv[2 * m + 2]);

#pragma unroll
                for (int tt = 0; tt < 5; ++tt)       // even dy = 2tt
#pragma unroll
                    for (int j = 0; j < 4; ++j)
                        FMA2(acc2[2 * tt][j], A.u[j], V.u[tt + j]);
#pragma unroll
                for (int tt = 0; tt < 4; ++tt)       // odd dy = 2tt+1
#pragma unroll
                    for (int j = 0; j < 4; ++j)
                        FMA2(acc2[2 * tt + 1][j], A.u[j], o[tt + j]);
            }
            if (lane == 0) mbar_arrive(smem_u32 + MB_EMPTY(s));
            if (++s == NSTAGE) { s = 0; ph ^= 1; }
        }

        // ---- per-tile epilogue ----
        const int h = h0 + hl;
#pragma unroll
        for (int dy = 0; dy < CC_ND; ++dy) {
            float f[8];
#pragma unroll
            for (int j = 0; j < 4; ++j)
                UNPACK2(f[2 * j], f[2 * j + 1], acc2[dy][j]);
            float4 r0, r1;
            r0.x = f[0] * inv; r0.y = f[1] * inv; r0.z = f[2] * inv; r0.w = f[3] * inv;
            r1.x = f[4] * inv; r1.y = f[5] * inv; r1.z = f[6] * inv; r1.w = f[7] * inv;
            float* op = &out[(((size_t)(b * CC_NOFF + dxi * CC_ND + dy) * CC_H) + h) * CC_W
                             + CC_PX * wg];
            ((float4*)op)[0] = r0;
            ((float4*)op)[1] = r1;
        }
    }
}

extern "C" void kernel_launch(void* const* d_in, const int* in_sizes, int n_in,
                              void* d_out, int out_size)
{
    const float* x1 = (const float*)d_in[0];
    const float* x2 = (const float*)d_in[1];
    float* out = (float*)d_out;

    cudaFuncSetAttribute(corr_kernel,
                         cudaFuncAttributeMaxDynamicSharedMemorySize, SMEM_BYTES);
    corr_kernel<<<NBLK, NTH, SMEM_BYTES>>>(x1, x2, out);
}